// round 11
// baseline (speedup 1.0000x reference)
#include <cuda_runtime.h>
#include <cuda_fp16.h>
#include <math.h>
#include <stdint.h>

// Problem constants
#define NB   64      // batch
#define NM   512     // memory slots
#define NE   256     // embedding dim
#define NT   32      // decode steps
#define NV   32000   // vocab
#define NTR  4       // tokens per memory slot
#define NG   768     // 3*NE gate dim
#define KX   512     // 2*NE vocab-GEMM K

// Output layout: [T,B,V] vocab | [T,B,M] ptr | [1,B,E] h
#define OUT_PTR  ((size_t)NT*NB*NV)
#define OUT_H    (OUT_PTR + (size_t)NT*NB*NM)

// ---------------- scratch ----------------
__device__ float g_mem[6ull*NB*NM*NE];   // 201 MB
__device__ float g_q  [NB*NE];
__device__ float g_H  [(size_t)NT*NB*NE];
__device__ float g_xin[(size_t)NT*NB*NE];
__device__ float g_gi [(size_t)NT*NB*NG];
__device__ float g_qc [(size_t)NT*NB*NE];
__device__ float g_O  [(size_t)NT*NB*NE];
__device__ float g_Sdump[(size_t)NT*NB*NM];
__device__ __half g_Wh[(size_t)NV*KX];
__device__ __half g_Xh[(size_t)NT*NB*KX];

// ---------------- 1) embedding sums (float2 vectorized, validated) -------------
__global__ void k_embed(const int* __restrict__ inp,
                        const float* __restrict__ encC,
                        const float* __restrict__ decC) {
    size_t idx = (size_t)blockIdx.x * 256 + threadIdx.x;  // over 6*NB*NM*(NE/2)
    int e2  = (int)(idx & 127);
    size_t r = idx >> 7;
    int bm  = (int)(r % (NB * NM));
    int tbl = (int)(r / (NB * NM));
    int b = bm / NM, m = bm % NM;
    const float* tab = (tbl < 3) ? (encC + (size_t)(tbl + 1) * NV * NE)
                                 : (decC + (size_t)(tbl - 3) * NV * NE);
    const float2* tab2 = (const float2*)tab;
    const int* ix = inp + ((size_t)m * NB + b) * NTR;
    float2 s = {0.f, 0.f};
    for (int tr = 0; tr < NTR; tr++) {
        float2 v = tab2[(size_t)ix[tr] * 128 + e2];
        s.x += v.x; s.y += v.y;
    }
    ((float2*)g_mem)[((size_t)tbl * NB * NM + bm) * 128 + e2] = s;
}

// ---------------- 2) encoder hop0 mean ----------------
__global__ void k_mean() {
    int b = blockIdx.x, e = threadIdx.x;
    const float* memb = g_mem + ((size_t)b * NM) * NE;
    float acc = 0.f;
    for (int m = 0; m < NM; m++) acc += memb[(size_t)m * NE + e];
    g_q[b * NE + e] = acc * (1.0f / NM);
}

// ---------------- encoder fused hop v2 (validated, 38us) -----------------------
__global__ void k_hop_enc(const float* __restrict__ Q, int tblS, int tblA,
                          float* __restrict__ O) {
    __shared__ float q[NE];
    __shared__ float sc[NM];
    __shared__ float red[40];
    __shared__ float part[4][NE];
    int b = blockIdx.x;
    int tid = threadIdx.x, w = tid >> 5, lane = tid & 31;   // 1024 threads
    if (tid < NE) q[tid] = Q[(size_t)b * NE + tid];
    __syncthreads();
    const float* MS = g_mem + ((size_t)tblS * NB * NM + (size_t)b * NM) * NE;
    for (int j = 0; j < 16; j++) {
        int m = w * 16 + j;
        const float* rowp = MS + (size_t)m * NE;
        float a = 0.f;
#pragma unroll
        for (int i = 0; i < 8; i++) a += rowp[i * 32 + lane] * q[i * 32 + lane];
#pragma unroll
        for (int off = 16; off; off >>= 1) a += __shfl_xor_sync(0xffffffffu, a, off);
        if (lane == 0) sc[m] = a;
    }
    __syncthreads();
    float v = 0.f, e = 0.f;
    if (tid < 512) {
        v = sc[tid];
        float mx = v;
#pragma unroll
        for (int off = 16; off; off >>= 1) mx = fmaxf(mx, __shfl_xor_sync(0xffffffffu, mx, off));
        if (lane == 0) red[w] = mx;
    }
    __syncthreads();
    if (tid == 0) {
        float m8 = red[0];
        for (int i = 1; i < 16; i++) m8 = fmaxf(m8, red[i]);
        red[32] = m8;
    }
    __syncthreads();
    if (tid < 512) {
        e = expf(v - red[32]);
        float s = e;
#pragma unroll
        for (int off = 16; off; off >>= 1) s += __shfl_xor_sync(0xffffffffu, s, off);
        if (lane == 0) red[16 + w] = s;
    }
    __syncthreads();
    if (tid == 0) {
        float t = 0.f;
        for (int i = 0; i < 16; i++) t += red[16 + i];
        red[33] = t;
    }
    __syncthreads();
    if (tid < 512) sc[tid] = e * (1.0f / red[33]);
    __syncthreads();
    const float* MA = g_mem + ((size_t)tblA * NB * NM + (size_t)b * NM) * NE;
    int qd = tid >> 8, ee = tid & 255;
    float acc = 0.f;
#pragma unroll 4
    for (int m = qd * 128; m < qd * 128 + 128; m++)
        acc += sc[m] * MA[(size_t)m * NE + ee];
    part[qd][ee] = acc;
    __syncthreads();
    if (tid < NE)
        O[(size_t)b * NE + tid] = q[tid] + part[0][tid] + part[1][tid]
                                         + part[2][tid] + part[3][tid];
}

// ---------------- batched decoder hop (validated) ----------------
__global__ void k_hop_dec(const float* __restrict__ Q, int tblS, int tblA,
                          float* __restrict__ O, float* __restrict__ Sout, int raw) {
    __shared__ float q[8][NE];
    __shared__ float sc[8][NM];
    int b = blockIdx.x, tg = blockIdx.y;
    int tid = threadIdx.x, w = tid >> 5, lane = tid & 31;
#pragma unroll
    for (int i = 0; i < 8; i++)
        q[i][tid] = Q[((size_t)(tg * 8 + i) * NB + b) * NE + tid];
    __syncthreads();
    const float* MS = g_mem + ((size_t)tblS * NB * NM + (size_t)b * NM) * NE;
    for (int j = 0; j < 64; j++) {
        int m = w * 64 + j;
        const float* rowp = MS + (size_t)m * NE;
        float mv[8];
#pragma unroll
        for (int i = 0; i < 8; i++) mv[i] = rowp[i * 32 + lane];
#pragma unroll
        for (int t = 0; t < 8; t++) {
            float a = 0.f;
#pragma unroll
            for (int i = 0; i < 8; i++) a += mv[i] * q[t][i * 32 + lane];
#pragma unroll
            for (int off = 16; off; off >>= 1) a += __shfl_xor_sync(0xffffffffu, a, off);
            if (lane == 0) sc[t][m] = a;
        }
    }
    __syncthreads();
    if (raw) {
#pragma unroll
        for (int t = 0; t < 8; t++) {
            Sout[((size_t)(tg * 8 + t) * NB + b) * NM + tid]       = sc[t][tid];
            Sout[((size_t)(tg * 8 + t) * NB + b) * NM + 256 + tid] = sc[t][tid + 256];
        }
        return;
    }
    {
        int t = w;
        float mx = -INFINITY;
#pragma unroll
        for (int i = 0; i < 16; i++) mx = fmaxf(mx, sc[t][i * 32 + lane]);
#pragma unroll
        for (int off = 16; off; off >>= 1) mx = fmaxf(mx, __shfl_xor_sync(0xffffffffu, mx, off));
        float ev[16], sum = 0.f;
#pragma unroll
        for (int i = 0; i < 16; i++) { ev[i] = expf(sc[t][i * 32 + lane] - mx); sum += ev[i]; }
#pragma unroll
        for (int off = 16; off; off >>= 1) sum += __shfl_xor_sync(0xffffffffu, sum, off);
        float inv = 1.0f / sum;
#pragma unroll
        for (int i = 0; i < 16; i++) sc[t][i * 32 + lane] = ev[i] * inv;
    }
    __syncthreads();
    const float* MA = g_mem + ((size_t)tblA * NB * NM + (size_t)b * NM) * NE;
    float acc[8] = {};
#pragma unroll 4
    for (int m = 0; m < NM; m++) {
        float mval = MA[(size_t)m * NE + tid];
#pragma unroll
        for (int t = 0; t < 8; t++) acc[t] += sc[t][m] * mval;
    }
#pragma unroll
    for (int t = 0; t < 8; t++)
        O[((size_t)(tg * 8 + t) * NB + b) * NE + tid] = acc[t];
}

// ---------------- decoder input embeddings ----------------
__global__ void k_xin(const int* __restrict__ tgt, const float* __restrict__ decC) {
    int tb = blockIdx.x;
    int t = tb / NB, b = tb % NB;
    int y = (t == 0) ? 2 : tgt[(t - 1) * NB + b];
    g_xin[(size_t)tb * NE + threadIdx.x] = decC[(size_t)y * NE + threadIdx.x];
}

// ---------------- register-tiled SGEMM (validated) for gi ----------------
__global__ __launch_bounds__(256, 2)
void k_sgemm(const float* __restrict__ A, const float* __restrict__ B,
             const float* __restrict__ bias, float* __restrict__ C,
             int M, int N, int K) {
    __shared__ float As[8][132];
    __shared__ float Bs[8][132];
    int tid = threadIdx.x;
    int m0 = blockIdx.y * 128, n0 = blockIdx.x * 128;
    int lr = tid >> 1;
    int lk = (tid & 1) * 4;
    const float* Ag = A + (size_t)(m0 + lr) * K + lk;
    const float* Bg = B + (size_t)(n0 + lr) * K + lk;
    int ty = tid >> 4, tx = tid & 15;
    float acc[8][8] = {};
    for (int k0 = 0; k0 < K; k0 += 8) {
        float4 av = *(const float4*)(Ag + k0);
        float4 bv = *(const float4*)(Bg + k0);
        As[lk + 0][lr] = av.x; As[lk + 1][lr] = av.y;
        As[lk + 2][lr] = av.z; As[lk + 3][lr] = av.w;
        Bs[lk + 0][lr] = bv.x; Bs[lk + 1][lr] = bv.y;
        Bs[lk + 2][lr] = bv.z; Bs[lk + 3][lr] = bv.w;
        __syncthreads();
#pragma unroll
        for (int kk = 0; kk < 8; kk++) {
            float a[8], b[8];
            *(float4*)&a[0] = *(const float4*)&As[kk][ty * 4];
            *(float4*)&a[4] = *(const float4*)&As[kk][64 + ty * 4];
            *(float4*)&b[0] = *(const float4*)&Bs[kk][tx * 4];
            *(float4*)&b[4] = *(const float4*)&Bs[kk][64 + tx * 4];
#pragma unroll
            for (int i = 0; i < 8; i++)
#pragma unroll
                for (int j = 0; j < 8; j++) acc[i][j] += a[i] * b[j];
        }
        __syncthreads();
    }
    float bb[8];
#pragma unroll
    for (int j = 0; j < 4; j++) {
        bb[j]     = bias[n0 + tx * 4 + j];
        bb[4 + j] = bias[n0 + 64 + tx * 4 + j];
    }
#pragma unroll
    for (int i = 0; i < 8; i++) {
        int m = m0 + ((i < 4) ? (ty * 4 + i) : (64 + ty * 4 + i - 4));
        float4 c0, c1;
        c0.x = acc[i][0] + bb[0]; c0.y = acc[i][1] + bb[1];
        c0.z = acc[i][2] + bb[2]; c0.w = acc[i][3] + bb[3];
        c1.x = acc[i][4] + bb[4]; c1.y = acc[i][5] + bb[5];
        c1.z = acc[i][6] + bb[6]; c1.w = acc[i][7] + bb[7];
        *(float4*)(C + (size_t)m * N + n0 + tx * 4) = c0;
        *(float4*)(C + (size_t)m * N + n0 + 64 + tx * 4) = c1;
    }
}

// ---------------- GRU (validated) ----------------
__global__ void k_gru(const float* __restrict__ Whh, const float* __restrict__ bhh,
                      float* __restrict__ out_h) {
    __shared__ float h[NE];
    __shared__ float gh[NG];
    int b = blockIdx.x, tid = threadIdx.x;
    if (tid < NE) h[tid] = g_q[b * NE + tid];
    __syncthreads();
    for (int t = 0; t < NT; t++) {
        float acc = bhh[tid];
        const float* w = Whh + (size_t)tid * NE;
#pragma unroll 8
        for (int k = 0; k < NE; k++) acc += w[k] * h[k];
        gh[tid] = acc;
        __syncthreads();
        if (tid < NE) {
            const float* gi = g_gi + ((size_t)t * NB + b) * NG;
            float r = 1.0f / (1.0f + expf(-(gi[tid] + gh[tid])));
            float z = 1.0f / (1.0f + expf(-(gi[NE + tid] + gh[NE + tid])));
            float n = tanhf(gi[2 * NE + tid] + r * gh[2 * NE + tid]);
            float hn = (1.0f - z) * n + z * h[tid];
            h[tid] = hn;
            g_H[((size_t)t * NB + b) * NE + tid] = hn;
            if (t == NT - 1) out_h[b * NE + tid] = hn;
        }
        __syncthreads();
    }
}

// ---------------- W_vocab -> fp16 ----------------
__global__ void k_cvt_w(const float* __restrict__ W) {
    size_t i = (size_t)blockIdx.x * 256 + threadIdx.x;
    g_Wh[i] = __float2half_rn(W[i]);
}

// ---------------- hop-0 fuse: qc = H+O0, X=[H|O0] -> fp16 ----------------
__global__ void k_fuse0() {
    int i = blockIdx.x * 256 + threadIdx.x;
    int e = i & (NE - 1);
    int tb = i >> 8;
    float hq = g_H[i], o = g_O[i];
    g_qc[i] = hq + o;
    size_t xi = (size_t)tb * KX + e;
    g_Xh[xi]      = __float2half_rn(hq);
    g_Xh[xi + NE] = __float2half_rn(o);
}

__global__ void k_add() {
    int i = blockIdx.x * 256 + threadIdx.x;
    g_qc[i] += g_O[i];
}

// ---------------- vocab GEMM v3: fp16 mma, high occupancy ----------------
// CTA tile 128m x 64n, 256 threads, 8 warps (4m x 2n), warp tile 32x32.
// acc = 32 floats/thread => ~75 regs => 3 CTAs/SM => 24 resident warps.
#define MMAH16816(d, a, b) \
  asm volatile("mma.sync.aligned.m16n8k16.row.col.f32.f16.f16.f32 " \
    "{%0,%1,%2,%3}, {%4,%5,%6,%7}, {%8,%9}, {%0,%1,%2,%3};" \
    : "+f"(d[0]), "+f"(d[1]), "+f"(d[2]), "+f"(d[3]) \
    : "r"(a[0]), "r"(a[1]), "r"(a[2]), "r"(a[3]), "r"(b[0]), "r"(b[1]))

__device__ __forceinline__ void cp16(uint32_t dst, const void* src) {
    asm volatile("cp.async.cg.shared.global [%0], [%1], 16;\n" :: "r"(dst), "l"(src));
}

// Stage (9216 B): A[128][24] halfs (6144 B) then B[64][24] halfs (3072 B).
// Rows of 24 halfs = 48 B (16B data x2 + 8B pad); LDS banks (g*12+tg)%32 distinct.
#define HG_STAGE 9216
#define HG_OFFB  6144
__global__ __launch_bounds__(256)
void k_hgemm(const float* __restrict__ bias, float* __restrict__ C) {
    __shared__ __align__(16) unsigned char sm[2 * HG_STAGE];
    int tid = threadIdx.x;
    int n0 = blockIdx.x * 64, m0 = blockIdx.y * 128;
    int wid = tid >> 5, lane = tid & 31;
    int wm = (wid >> 1) * 32, wn = (wid & 1) * 32;
    int g = lane >> 2, tg = lane & 3;
    uint32_t sbase = (uint32_t)__cvta_generic_to_shared(sm);
    int lr = tid >> 1, lkc = tid & 1;   // A: row 0..127, 16B chunk 0..1

    const __half* srcA = g_Xh + (size_t)(m0 + lr) * KX + lkc * 8;
    const __half* srcB = g_Wh + (size_t)(n0 + (lr & 63)) * KX + lkc * 8;
    uint32_t dA = sbase + lr * 48 + lkc * 16;
    uint32_t dB = sbase + HG_OFFB + (lr & 63) * 48 + lkc * 16;
    bool doB = (tid < 128);

    float acc[2][4][4] = {};

    // prologue: stages 0 and 1 (k-chunks 0, 1)
    cp16(dA, srcA);
    if (doB) cp16(dB, srcB);
    asm volatile("cp.async.commit_group;\n" ::);
    cp16(dA + HG_STAGE, srcA + 16);
    if (doB) cp16(dB + HG_STAGE, srcB + 16);
    asm volatile("cp.async.commit_group;\n" ::);

    for (int it = 0; it < KX / 16; it++) {
        if (it + 2 < KX / 16) {
            uint32_t off = (uint32_t)(it & 1) * HG_STAGE;
            int koff = (it + 2) * 16;
            // wait for stage `it` (2 groups in flight after this fill? order: we
            // first wait so stage (it&1) is free to overwrite is WRONG — must
            // wait for compute stage first. Standard order: wait, sync, compute,
            // then refill. Here: wait_group 1 leaves newest in flight.
        }
        asm volatile("cp.async.wait_group 1;\n" ::);
        __syncthreads();
        const char* sb = (const char*)sm + (it & 1) * HG_STAGE;
        const __half* Ah = (const __half*)(sb);
        const __half* Bh = (const __half*)(sb + HG_OFFB);
        int c = tg * 2;
        uint32_t ah[2][4];
#pragma unroll
        for (int f = 0; f < 2; f++) {
            int r = wm + f * 16 + g;
            ah[f][0] = *(const uint32_t*)&Ah[r * 24 + c];
            ah[f][1] = *(const uint32_t*)&Ah[(r + 8) * 24 + c];
            ah[f][2] = *(const uint32_t*)&Ah[r * 24 + c + 8];
            ah[f][3] = *(const uint32_t*)&Ah[(r + 8) * 24 + c + 8];
        }
#pragma unroll
        for (int fn = 0; fn < 4; fn++) {
            int r = wn + fn * 8 + g;
            uint32_t bh[2];
            bh[0] = *(const uint32_t*)&Bh[r * 24 + c];
            bh[1] = *(const uint32_t*)&Bh[r * 24 + c + 8];
            MMAH16816(acc[0][fn], ah[0], bh);
            MMAH16816(acc[1][fn], ah[1], bh);
        }
        __syncthreads();
        if (it + 2 < KX / 16) {
            uint32_t off = (uint32_t)(it & 1) * HG_STAGE;
            int koff = (it + 2) * 16;
            cp16(dA + off, srcA + koff);
            if (doB) cp16(dB + off, srcB + koff);
            asm volatile("cp.async.commit_group;\n" ::);
        } else {
            // keep group count balanced for wait_group 1 semantics
            asm volatile("cp.async.commit_group;\n" ::);
        }
    }
#pragma unroll
    for (int f = 0; f < 2; f++) {
        int rbase = m0 + wm + f * 16 + g;
#pragma unroll
        for (int fn = 0; fn < 4; fn++) {
            int c0 = n0 + wn + fn * 8 + tg * 2;
            float b0v = bias[c0], b1v = bias[c0 + 1];
            float2 v0 = {acc[f][fn][0] + b0v, acc[f][fn][1] + b1v};
            float2 v1 = {acc[f][fn][2] + b0v, acc[f][fn][3] + b1v};
            *(float2*)(C + (size_t)rbase * NV + c0) = v0;
            *(float2*)(C + (size_t)(rbase + 8) * NV + c0) = v1;
        }
    }
}

// ---------------- launch ----------------
extern "C" void kernel_launch(void* const* d_in, const int* in_sizes, int n_in,
                              void* d_out, int out_size) {
    const int*   inp    = (const int*)d_in[0];
    const int*   tgt    = (const int*)d_in[1];
    const float* encC   = (const float*)d_in[2];
    const float* decC   = (const float*)d_in[3];
    const float* W_ih   = (const float*)d_in[4];
    const float* W_hh   = (const float*)d_in[5];
    const float* b_ih   = (const float*)d_in[6];
    const float* b_hh   = (const float*)d_in[7];
    const float* W_voc  = (const float*)d_in[8];
    const float* b_voc  = (const float*)d_in[9];
    float* out = (float*)d_out;

    float *gq, *gO, *gH, *gqc, *gS0, *gxin, *ggi;
    cudaGetSymbolAddress((void**)&gq,   g_q);
    cudaGetSymbolAddress((void**)&gO,   g_O);
    cudaGetSymbolAddress((void**)&gH,   g_H);
    cudaGetSymbolAddress((void**)&gqc,  g_qc);
    cudaGetSymbolAddress((void**)&gS0,  g_Sdump);
    cudaGetSymbolAddress((void**)&gxin, g_xin);
    cudaGetSymbolAddress((void**)&ggi,  g_gi);

    // W_vocab fp16 conversion
    k_cvt_w<<<(unsigned)(((size_t)NV * KX) / 256), 256>>>(W_voc);

    // embeddings for 6 needed tables
    k_embed<<<(unsigned)((6ull * NB * NM * (NE / 2)) / 256), 256>>>(inp, encC, decC);

    // ---- encoder: hop0 mean, then 2 fused hops ----
    k_mean<<<NB, 256>>>();
    k_hop_enc<<<NB, 1024>>>(gq, 0, 1, gq);
    k_hop_enc<<<NB, 1024>>>(gq, 1, 2, gq);

    // ---- decoder setup + GRU ----
    k_xin<<<NT * NB, NE>>>(tgt, decC);
    k_sgemm<<<dim3(NG / 128, (NT * NB) / 128), 256>>>(gxin, W_ih, b_ih, ggi, NT * NB, NG, NE);
    k_gru<<<NB, NG>>>(W_hh, b_hh, out + OUT_H);

    // ---- decoder hop 0 (batched) -> O0; build qc and fp16 X ----
    k_hop_dec<<<dim3(NB, NT / 8), 256>>>(gH, 3, 4, gO, gS0, 0);
    k_fuse0<<<(NT * NB * NE) / 256, 256>>>();

    // ---- vocab logits: fp16 tensor-core GEMM, high-occupancy tiling ----
    k_hgemm<<<dim3(NV / 64, (NT * NB) / 128), 256>>>(b_voc, out);

    // ---- decoder hop 1 (batched) ----
    k_hop_dec<<<dim3(NB, NT / 8), 256>>>(gqc, 4, 5, gO, gS0, 0);
    k_add<<<(NT * NB * NE) / 256, 256>>>();
    // ---- decoder hop 2: raw scores -> all_ptr ----
    k_hop_dec<<<dim3(NB, NT / 8), 256>>>(gqc, 5, 5, gO, out + OUT_PTR, 1);
}

// round 12
// speedup vs baseline: 3.1893x; 3.1893x over previous
#include <cuda_runtime.h>
#include <cuda_fp16.h>
#include <math.h>
#include <stdint.h>

// Problem constants
#define NB   64      // batch
#define NM   512     // memory slots
#define NE   256     // embedding dim
#define NT   32      // decode steps
#define NV   32000   // vocab
#define NTR  4       // tokens per memory slot
#define NG   768     // 3*NE gate dim
#define KX   512     // 2*NE vocab-GEMM K

// Output layout: [T,B,V] vocab | [T,B,M] ptr | [1,B,E] h
#define OUT_PTR  ((size_t)NT*NB*NV)
#define OUT_H    (OUT_PTR + (size_t)NT*NB*NM)

// ---------------- scratch ----------------
__device__ float g_mem[6ull*NB*NM*NE];   // 201 MB
__device__ float g_q  [NB*NE];
__device__ float g_H  [(size_t)NT*NB*NE];
__device__ float g_xin[(size_t)NT*NB*NE];
__device__ float g_gi [(size_t)NT*NB*NG];
__device__ float g_qc [(size_t)NT*NB*NE];
__device__ float g_O  [(size_t)NT*NB*NE];
__device__ float g_Sdump[(size_t)NT*NB*NM];
__device__ float g_Wt [(size_t)NE*NG];   // W_hh transposed: g_Wt[k*NG+j] = W_hh[j,k]
__device__ __half g_Wh[(size_t)NV*KX];
__device__ __half g_Xh[(size_t)NT*NB*KX];

// ---------------- 1) embedding sums (float4 vectorized) ----------------
__global__ void k_embed(const int* __restrict__ inp,
                        const float* __restrict__ encC,
                        const float* __restrict__ decC) {
    size_t idx = (size_t)blockIdx.x * 256 + threadIdx.x;  // over 6*NB*NM*64
    int e4  = (int)(idx & 63);           // float4 index within row
    size_t r = idx >> 6;
    int bm  = (int)(r % (NB * NM));
    int tbl = (int)(r / (NB * NM));
    int b = bm / NM, m = bm % NM;
    const float* tab = (tbl < 3) ? (encC + (size_t)(tbl + 1) * NV * NE)
                                 : (decC + (size_t)(tbl - 3) * NV * NE);
    const float4* tab4 = (const float4*)tab;
    const int* ix = inp + ((size_t)m * NB + b) * NTR;
    float4 s = {0.f, 0.f, 0.f, 0.f};
    for (int tr = 0; tr < NTR; tr++) {
        float4 v = tab4[(size_t)ix[tr] * 64 + e4];
        s.x += v.x; s.y += v.y; s.z += v.z; s.w += v.w;
    }
    ((float4*)g_mem)[((size_t)tbl * NB * NM + bm) * 64 + e4] = s;
}

// ---------------- W_hh transpose (tiled, coalesced both sides) -----------------
__global__ void k_whh_t(const float* __restrict__ W) {
    __shared__ float t[32][33];
    int j0 = blockIdx.x * 32, k0 = blockIdx.y * 32;
    t[threadIdx.y][threadIdx.x] = W[(size_t)(j0 + threadIdx.y) * NE + k0 + threadIdx.x];
    __syncthreads();
    g_Wt[(size_t)(k0 + threadIdx.y) * NG + j0 + threadIdx.x] = t[threadIdx.x][threadIdx.y];
}

// ---------------- 2) encoder hop0 mean ----------------
__global__ void k_mean() {
    int b = blockIdx.x, e = threadIdx.x;
    const float* memb = g_mem + ((size_t)b * NM) * NE;
    float acc = 0.f;
    for (int m = 0; m < NM; m++) acc += memb[(size_t)m * NE + e];
    g_q[b * NE + e] = acc * (1.0f / NM);
}

// ---------------- encoder fused hop v2 (validated, 38us) -----------------------
__global__ void k_hop_enc(const float* __restrict__ Q, int tblS, int tblA,
                          float* __restrict__ O) {
    __shared__ float q[NE];
    __shared__ float sc[NM];
    __shared__ float red[40];
    __shared__ float part[4][NE];
    int b = blockIdx.x;
    int tid = threadIdx.x, w = tid >> 5, lane = tid & 31;   // 1024 threads
    if (tid < NE) q[tid] = Q[(size_t)b * NE + tid];
    __syncthreads();
    const float* MS = g_mem + ((size_t)tblS * NB * NM + (size_t)b * NM) * NE;
    for (int j = 0; j < 16; j++) {
        int m = w * 16 + j;
        const float* rowp = MS + (size_t)m * NE;
        float a = 0.f;
#pragma unroll
        for (int i = 0; i < 8; i++) a += rowp[i * 32 + lane] * q[i * 32 + lane];
#pragma unroll
        for (int off = 16; off; off >>= 1) a += __shfl_xor_sync(0xffffffffu, a, off);
        if (lane == 0) sc[m] = a;
    }
    __syncthreads();
    float v = 0.f, e = 0.f;
    if (tid < 512) {
        v = sc[tid];
        float mx = v;
#pragma unroll
        for (int off = 16; off; off >>= 1) mx = fmaxf(mx, __shfl_xor_sync(0xffffffffu, mx, off));
        if (lane == 0) red[w] = mx;
    }
    __syncthreads();
    if (tid == 0) {
        float m8 = red[0];
        for (int i = 1; i < 16; i++) m8 = fmaxf(m8, red[i]);
        red[32] = m8;
    }
    __syncthreads();
    if (tid < 512) {
        e = expf(v - red[32]);
        float s = e;
#pragma unroll
        for (int off = 16; off; off >>= 1) s += __shfl_xor_sync(0xffffffffu, s, off);
        if (lane == 0) red[16 + w] = s;
    }
    __syncthreads();
    if (tid == 0) {
        float t = 0.f;
        for (int i = 0; i < 16; i++) t += red[16 + i];
        red[33] = t;
    }
    __syncthreads();
    if (tid < 512) sc[tid] = e * (1.0f / red[33]);
    __syncthreads();
    const float* MA = g_mem + ((size_t)tblA * NB * NM + (size_t)b * NM) * NE;
    int qd = tid >> 8, ee = tid & 255;
    float acc = 0.f;
#pragma unroll 4
    for (int m = qd * 128; m < qd * 128 + 128; m++)
        acc += sc[m] * MA[(size_t)m * NE + ee];
    part[qd][ee] = acc;
    __syncthreads();
    if (tid < NE)
        O[(size_t)b * NE + tid] = q[tid] + part[0][tid] + part[1][tid]
                                         + part[2][tid] + part[3][tid];
}

// ---------------- batched decoder hop (validated) ----------------
__global__ void k_hop_dec(const float* __restrict__ Q, int tblS, int tblA,
                          float* __restrict__ O, float* __restrict__ Sout, int raw) {
    __shared__ float q[8][NE];
    __shared__ float sc[8][NM];
    int b = blockIdx.x, tg = blockIdx.y;
    int tid = threadIdx.x, w = tid >> 5, lane = tid & 31;
#pragma unroll
    for (int i = 0; i < 8; i++)
        q[i][tid] = Q[((size_t)(tg * 8 + i) * NB + b) * NE + tid];
    __syncthreads();
    const float* MS = g_mem + ((size_t)tblS * NB * NM + (size_t)b * NM) * NE;
    for (int j = 0; j < 64; j++) {
        int m = w * 64 + j;
        const float* rowp = MS + (size_t)m * NE;
        float mv[8];
#pragma unroll
        for (int i = 0; i < 8; i++) mv[i] = rowp[i * 32 + lane];
#pragma unroll
        for (int t = 0; t < 8; t++) {
            float a = 0.f;
#pragma unroll
            for (int i = 0; i < 8; i++) a += mv[i] * q[t][i * 32 + lane];
#pragma unroll
            for (int off = 16; off; off >>= 1) a += __shfl_xor_sync(0xffffffffu, a, off);
            if (lane == 0) sc[t][m] = a;
        }
    }
    __syncthreads();
    if (raw) {
#pragma unroll
        for (int t = 0; t < 8; t++) {
            Sout[((size_t)(tg * 8 + t) * NB + b) * NM + tid]       = sc[t][tid];
            Sout[((size_t)(tg * 8 + t) * NB + b) * NM + 256 + tid] = sc[t][tid + 256];
        }
        return;
    }
    {
        int t = w;
        float mx = -INFINITY;
#pragma unroll
        for (int i = 0; i < 16; i++) mx = fmaxf(mx, sc[t][i * 32 + lane]);
#pragma unroll
        for (int off = 16; off; off >>= 1) mx = fmaxf(mx, __shfl_xor_sync(0xffffffffu, mx, off));
        float ev[16], sum = 0.f;
#pragma unroll
        for (int i = 0; i < 16; i++) { ev[i] = expf(sc[t][i * 32 + lane] - mx); sum += ev[i]; }
#pragma unroll
        for (int off = 16; off; off >>= 1) sum += __shfl_xor_sync(0xffffffffu, sum, off);
        float inv = 1.0f / sum;
#pragma unroll
        for (int i = 0; i < 16; i++) sc[t][i * 32 + lane] = ev[i] * inv;
    }
    __syncthreads();
    const float* MA = g_mem + ((size_t)tblA * NB * NM + (size_t)b * NM) * NE;
    float acc[8] = {};
#pragma unroll 4
    for (int m = 0; m < NM; m++) {
        float mval = MA[(size_t)m * NE + tid];
#pragma unroll
        for (int t = 0; t < 8; t++) acc[t] += sc[t][m] * mval;
    }
#pragma unroll
    for (int t = 0; t < 8; t++)
        O[((size_t)(tg * 8 + t) * NB + b) * NE + tid] = acc[t];
}

// ---------------- decoder input embeddings ----------------
__global__ void k_xin(const int* __restrict__ tgt, const float* __restrict__ decC) {
    int tb = blockIdx.x;
    int t = tb / NB, b = tb % NB;
    int y = (t == 0) ? 2 : tgt[(t - 1) * NB + b];
    g_xin[(size_t)tb * NE + threadIdx.x] = decC[(size_t)y * NE + threadIdx.x];
}

// ---------------- register-tiled SGEMM (validated) for gi ----------------
__global__ __launch_bounds__(256, 2)
void k_sgemm(const float* __restrict__ A, const float* __restrict__ B,
             const float* __restrict__ bias, float* __restrict__ C,
             int M, int N, int K) {
    __shared__ float As[8][132];
    __shared__ float Bs[8][132];
    int tid = threadIdx.x;
    int m0 = blockIdx.y * 128, n0 = blockIdx.x * 128;
    int lr = tid >> 1;
    int lk = (tid & 1) * 4;
    const float* Ag = A + (size_t)(m0 + lr) * K + lk;
    const float* Bg = B + (size_t)(n0 + lr) * K + lk;
    int ty = tid >> 4, tx = tid & 15;
    float acc[8][8] = {};
    for (int k0 = 0; k0 < K; k0 += 8) {
        float4 av = *(const float4*)(Ag + k0);
        float4 bv = *(const float4*)(Bg + k0);
        As[lk + 0][lr] = av.x; As[lk + 1][lr] = av.y;
        As[lk + 2][lr] = av.z; As[lk + 3][lr] = av.w;
        Bs[lk + 0][lr] = bv.x; Bs[lk + 1][lr] = bv.y;
        Bs[lk + 2][lr] = bv.z; Bs[lk + 3][lr] = bv.w;
        __syncthreads();
#pragma unroll
        for (int kk = 0; kk < 8; kk++) {
            float a[8], b[8];
            *(float4*)&a[0] = *(const float4*)&As[kk][ty * 4];
            *(float4*)&a[4] = *(const float4*)&As[kk][64 + ty * 4];
            *(float4*)&b[0] = *(const float4*)&Bs[kk][tx * 4];
            *(float4*)&b[4] = *(const float4*)&Bs[kk][64 + tx * 4];
#pragma unroll
            for (int i = 0; i < 8; i++)
#pragma unroll
                for (int j = 0; j < 8; j++) acc[i][j] += a[i] * b[j];
        }
        __syncthreads();
    }
    float bb[8];
#pragma unroll
    for (int j = 0; j < 4; j++) {
        bb[j]     = bias[n0 + tx * 4 + j];
        bb[4 + j] = bias[n0 + 64 + tx * 4 + j];
    }
#pragma unroll
    for (int i = 0; i < 8; i++) {
        int m = m0 + ((i < 4) ? (ty * 4 + i) : (64 + ty * 4 + i - 4));
        float4 c0, c1;
        c0.x = acc[i][0] + bb[0]; c0.y = acc[i][1] + bb[1];
        c0.z = acc[i][2] + bb[2]; c0.w = acc[i][3] + bb[3];
        c1.x = acc[i][4] + bb[4]; c1.y = acc[i][5] + bb[5];
        c1.z = acc[i][6] + bb[6]; c1.w = acc[i][7] + bb[7];
        *(float4*)(C + (size_t)m * N + n0 + tx * 4) = c0;
        *(float4*)(C + (size_t)m * N + n0 + 64 + tx * 4) = c1;
    }
}

// ---------------- GRU v2: coalesced transposed-W reads ----------------
// Per k, warp reads g_Wt[k*NG + tid..tid+31] = one contiguous 128B line.
__global__ void k_gru(const float* __restrict__ bhh, float* __restrict__ out_h) {
    __shared__ float h[NE];
    __shared__ float gh[NG];
    int b = blockIdx.x, tid = threadIdx.x;   // 768 threads, one gate row each
    if (tid < NE) h[tid] = g_q[b * NE + tid];
    float bias = bhh[tid];
    __syncthreads();
    for (int t = 0; t < NT; t++) {
        float acc = bias;
#pragma unroll 8
        for (int k = 0; k < NE; k++)
            acc += g_Wt[(size_t)k * NG + tid] * h[k];
        gh[tid] = acc;
        __syncthreads();
        if (tid < NE) {
            const float* gi = g_gi + ((size_t)t * NB + b) * NG;
            float r = 1.0f / (1.0f + expf(-(gi[tid] + gh[tid])));
            float z = 1.0f / (1.0f + expf(-(gi[NE + tid] + gh[NE + tid])));
            float n = tanhf(gi[2 * NE + tid] + r * gh[2 * NE + tid]);
            float hn = (1.0f - z) * n + z * h[tid];
            h[tid] = hn;
            g_H[((size_t)t * NB + b) * NE + tid] = hn;
            if (t == NT - 1) out_h[b * NE + tid] = hn;
        }
        __syncthreads();
    }
}

// ---------------- W_vocab -> fp16 ----------------
__global__ void k_cvt_w(const float* __restrict__ W) {
    size_t i = (size_t)blockIdx.x * 256 + threadIdx.x;
    g_Wh[i] = __float2half_rn(W[i]);
}

// ---------------- hop-0 fuse: qc = H+O0, X=[H|O0] -> fp16 ----------------
__global__ void k_fuse0() {
    int i = blockIdx.x * 256 + threadIdx.x;
    int e = i & (NE - 1);
    int tb = i >> 8;
    float hq = g_H[i], o = g_O[i];
    g_qc[i] = hq + o;
    size_t xi = (size_t)tb * KX + e;
    g_Xh[xi]      = __float2half_rn(hq);
    g_Xh[xi + NE] = __float2half_rn(o);
}

__global__ void k_add() {
    int i = blockIdx.x * 256 + threadIdx.x;
    g_qc[i] += g_O[i];
}

// ---------------- vocab GEMM (R10 best): fp16 mma + cp.async double buffer -----
#define MMAH16816(d, a, b) \
  asm volatile("mma.sync.aligned.m16n8k16.row.col.f32.f16.f16.f32 " \
    "{%0,%1,%2,%3}, {%4,%5,%6,%7}, {%8,%9}, {%0,%1,%2,%3};" \
    : "+f"(d[0]), "+f"(d[1]), "+f"(d[2]), "+f"(d[3]) \
    : "r"(a[0]), "r"(a[1]), "r"(a[2]), "r"(a[3]), "r"(b[0]), "r"(b[1]))

__device__ __forceinline__ void cp16(uint32_t dst, const void* src) {
    asm volatile("cp.async.cg.shared.global [%0], [%1], 16;\n" :: "r"(dst), "l"(src));
}

// Stage (12288 B): A[128][24], B[128][24] (rows of 24 half = 48 B: 16 data + 8 pad)
__global__ __launch_bounds__(256)
void k_hgemm(const float* __restrict__ bias, float* __restrict__ C) {
    __shared__ __align__(16) unsigned char sm[24576];   // 2 stages x 12288
    int tid = threadIdx.x;
    int n0 = blockIdx.x * 128, m0 = blockIdx.y * 128;
    int wid = tid >> 5, lane = tid & 31;
    int wm = (wid >> 2) * 64, wn = (wid & 3) * 32;
    int g = lane >> 2, tg = lane & 3;
    uint32_t sbase = (uint32_t)__cvta_generic_to_shared(sm);
    int lr = tid >> 1, lkc = tid & 1;   // row 0..127, 16B chunk 0..1

    const __half* srcA = g_Xh + (size_t)(m0 + lr) * KX + lkc * 8;
    const __half* srcB = g_Wh + (size_t)(n0 + lr) * KX + lkc * 8;
    uint32_t dbase = sbase + lr * 48 + lkc * 16;

    float acc[4][4][4] = {};

    cp16(dbase,        srcA);
    cp16(dbase + 6144, srcB);
    asm volatile("cp.async.commit_group;\n" ::);

    for (int it = 0; it < KX / 16; it++) {
        if (it + 1 < KX / 16) {
            uint32_t d2 = dbase + ((it + 1) & 1) * 12288;
            int koff = (it + 1) * 16;
            cp16(d2,        srcA + koff);
            cp16(d2 + 6144, srcB + koff);
            asm volatile("cp.async.commit_group;\n" ::);
            asm volatile("cp.async.wait_group 1;\n" ::);
        } else {
            asm volatile("cp.async.wait_group 0;\n" ::);
        }
        __syncthreads();
        const char* sb = (const char*)sm + (it & 1) * 12288;
        const __half* Ah = (const __half*)(sb);
        const __half* Bh = (const __half*)(sb + 6144);
        uint32_t ah[4][4];
        int c = tg * 2;
#pragma unroll
        for (int f = 0; f < 4; f++) {
            int r = wm + f * 16 + g;
            ah[f][0] = *(const uint32_t*)&Ah[r * 24 + c];
            ah[f][1] = *(const uint32_t*)&Ah[(r + 8) * 24 + c];
            ah[f][2] = *(const uint32_t*)&Ah[r * 24 + c + 8];
            ah[f][3] = *(const uint32_t*)&Ah[(r + 8) * 24 + c + 8];
        }
#pragma unroll
        for (int fn = 0; fn < 4; fn++) {
            int r = wn + fn * 8 + g;
            uint32_t bh[2];
            bh[0] = *(const uint32_t*)&Bh[r * 24 + c];
            bh[1] = *(const uint32_t*)&Bh[r * 24 + c + 8];
#pragma unroll
            for (int f = 0; f < 4; f++)
                MMAH16816(acc[f][fn], ah[f], bh);
        }
        __syncthreads();
    }
#pragma unroll
    for (int f = 0; f < 4; f++) {
        int rbase = m0 + wm + f * 16 + g;
#pragma unroll
        for (int fn = 0; fn < 4; fn++) {
            int c0 = n0 + wn + fn * 8 + tg * 2;
            float b0v = bias[c0], b1v = bias[c0 + 1];
            float2 v0 = {acc[f][fn][0] + b0v, acc[f][fn][1] + b1v};
            float2 v1 = {acc[f][fn][2] + b0v, acc[f][fn][3] + b1v};
            *(float2*)(C + (size_t)rbase * NV + c0) = v0;
            *(float2*)(C + (size_t)(rbase + 8) * NV + c0) = v1;
        }
    }
}

// ---------------- launch ----------------
extern "C" void kernel_launch(void* const* d_in, const int* in_sizes, int n_in,
                              void* d_out, int out_size) {
    const int*   inp    = (const int*)d_in[0];
    const int*   tgt    = (const int*)d_in[1];
    const float* encC   = (const float*)d_in[2];
    const float* decC   = (const float*)d_in[3];
    const float* W_ih   = (const float*)d_in[4];
    const float* W_hh   = (const float*)d_in[5];
    const float* b_ih   = (const float*)d_in[6];
    const float* b_hh   = (const float*)d_in[7];
    const float* W_voc  = (const float*)d_in[8];
    const float* b_voc  = (const float*)d_in[9];
    float* out = (float*)d_out;

    float *gq, *gO, *gH, *gqc, *gS0, *gxin, *ggi;
    cudaGetSymbolAddress((void**)&gq,   g_q);
    cudaGetSymbolAddress((void**)&gO,   g_O);
    cudaGetSymbolAddress((void**)&gH,   g_H);
    cudaGetSymbolAddress((void**)&gqc,  g_qc);
    cudaGetSymbolAddress((void**)&gS0,  g_Sdump);
    cudaGetSymbolAddress((void**)&gxin, g_xin);
    cudaGetSymbolAddress((void**)&ggi,  g_gi);

    // dependency-free setup first; k_embed lands at launch idx 3 (the ncu slot)
    k_cvt_w<<<(unsigned)(((size_t)NV * KX) / 256), 256>>>(W_voc);            // 0
    k_whh_t<<<dim3(NG / 32, NE / 32), dim3(32, 32)>>>(W_hh);                 // 1
    k_xin<<<NT * NB, NE>>>(tgt, decC);                                       // 2
    k_embed<<<(unsigned)((6ull * NB * NM * 64) / 256), 256>>>(inp, encC, decC); // 3 (profiled)

    // ---- encoder: hop0 mean, then 2 fused hops ----
    k_mean<<<NB, 256>>>();
    k_hop_enc<<<NB, 1024>>>(gq, 0, 1, gq);
    k_hop_enc<<<NB, 1024>>>(gq, 1, 2, gq);

    // ---- decoder setup + GRU (coalesced transposed W) ----
    k_sgemm<<<dim3(NG / 128, (NT * NB) / 128), 256>>>(gxin, W_ih, b_ih, ggi, NT * NB, NG, NE);
    k_gru<<<NB, NG>>>(b_hh, out + OUT_H);

    // ---- decoder hop 0 (batched) -> O0; build qc and fp16 X ----
    k_hop_dec<<<dim3(NB, NT / 8), 256>>>(gH, 3, 4, gO, gS0, 0);
    k_fuse0<<<(NT * NB * NE) / 256, 256>>>();

    // ---- vocab logits: fp16 tensor-core GEMM (R10 config) ----
    k_hgemm<<<dim3(NV / 128, (NT * NB) / 128), 256>>>(b_voc, out);

    // ---- decoder hop 1 (batched) ----
    k_hop_dec<<<dim3(NB, NT / 8), 256>>>(gqc, 4, 5, gO, gS0, 0);
    k_add<<<(NT * NB * NE) / 256, 256>>>();
    // ---- decoder hop 2: raw scores -> all_ptr ----
    k_hop_dec<<<dim3(NB, NT / 8), 256>>>(gqc, 5, 5, gO, out + OUT_PTR, 1);
}